// round 3
// baseline (speedup 1.0000x reference)
#include <cuda_runtime.h>
#include <cuda_bf16.h>

#define MAX_N 100000

__device__ float g_h[MAX_N];     // x @ W, [N]
__device__ float g_dinv[MAX_N];  // deg^{-1/2}, [N]
__device__ int   g_deg[MAX_N];   // neighbor count (excl. self-loop)

// Kernel 1: h[i] = dot(x[i,:], W). One warp per node. Also zeroes g_deg.
__global__ void k_linear(const float* __restrict__ x,
                         const float* __restrict__ W,
                         int N, int D) {
    int gtid = blockIdx.x * blockDim.x + threadIdx.x;
    if (gtid < N) g_deg[gtid] = 0;

    int warp = gtid >> 5;
    int lane = gtid & 31;
    if (warp >= N) return;

    const float4* xr = reinterpret_cast<const float4*>(x + (size_t)warp * D);
    const float4* wr = reinterpret_cast<const float4*>(W);
    int nv = D >> 2;  // 128 float4 per row for D=512
    float acc = 0.0f;
    for (int j = lane; j < nv; j += 32) {
        float4 a = xr[j];
        float4 b = __ldg(&wr[j]);
        acc += a.x * b.x + a.y * b.y + a.z * b.z + a.w * b.w;
    }
#pragma unroll
    for (int o = 16; o; o >>= 1)
        acc += __shfl_xor_sync(0xffffffffu, acc, o);
    if (lane == 0) g_h[warp] = acc;
}

// Kernel 2: degree count over destination nodes (int4-vectorized body).
__global__ void k_deg(const int* __restrict__ dst, int E) {
    int stride = gridDim.x * blockDim.x;
    int t = blockIdx.x * blockDim.x + threadIdx.x;
    int E4 = E >> 2;
    const int4* d4 = reinterpret_cast<const int4*>(dst);
    for (int j = t; j < E4; j += stride) {
        int4 d = __ldg(&d4[j]);
        atomicAdd(&g_deg[d.x], 1);
        atomicAdd(&g_deg[d.y], 1);
        atomicAdd(&g_deg[d.z], 1);
        atomicAdd(&g_deg[d.w], 1);
    }
    // scalar tail (no alignment assumption)
    int base = E4 << 2;
    for (int j = base + t; j < E; j += stride)
        atomicAdd(&g_deg[__ldg(&dst[j])], 1);
}

// Kernel 3: dinv = rsqrt(deg+1); out initialized with self-loop term h/(deg+1).
__global__ void k_norm(float* __restrict__ out, int N) {
    int i = blockIdx.x * blockDim.x + threadIdx.x;
    if (i >= N) return;
    float deg = (float)(g_deg[i] + 1);  // +1 self-loop, always >= 1
    float di = rsqrtf(deg);
    g_dinv[i] = di;
    out[i] = g_h[i] * di * di;  // = h[i]/deg: self-loop message
}

// Kernel 4: per-edge message + scatter-add (int4-vectorized index reads).
__global__ void k_edge(const int* __restrict__ src,
                       const int* __restrict__ dst,
                       float* __restrict__ out, int E) {
    int stride = gridDim.x * blockDim.x;
    int t = blockIdx.x * blockDim.x + threadIdx.x;
    int E4 = E >> 2;
    const int4* s4 = reinterpret_cast<const int4*>(src);
    const int4* d4 = reinterpret_cast<const int4*>(dst);
    for (int j = t; j < E4; j += stride) {
        int4 s = __ldg(&s4[j]);
        int4 d = __ldg(&d4[j]);
        atomicAdd(&out[d.x], g_dinv[s.x] * g_dinv[d.x] * g_h[s.x]);
        atomicAdd(&out[d.y], g_dinv[s.y] * g_dinv[d.y] * g_h[s.y]);
        atomicAdd(&out[d.z], g_dinv[s.z] * g_dinv[d.z] * g_h[s.z]);
        atomicAdd(&out[d.w], g_dinv[s.w] * g_dinv[d.w] * g_h[s.w]);
    }
    int base = E4 << 2;
    for (int j = base + t; j < E; j += stride) {
        int s = __ldg(&src[j]);
        int d = __ldg(&dst[j]);
        atomicAdd(&out[d], g_dinv[s] * g_dinv[d] * g_h[s]);
    }
}

extern "C" void kernel_launch(void* const* d_in, const int* in_sizes, int n_in,
                              void* d_out, int out_size) {
    const float* x  = (const float*)d_in[0];
    const int*   ei = (const int*)d_in[1];
    const float* W  = (const float*)d_in[2];
    float* out = (float*)d_out;

    int D = in_sizes[2];               // W is [D,1] -> 512 elements
    if (D <= 0 || (D & 3)) return;     // defensive: need float4-divisible D
    int N = in_sizes[0] / D;           // 100000
    if (N <= 0 || N > MAX_N || N != out_size) return;  // avoid OOB on globals
    int E = in_sizes[1] / 2;           // 3200000
    const int* src = ei;               // edge_index[0]
    const int* dst = ei + E;           // edge_index[1]

    // 1. linear transform (one warp per node) + zero degrees
    {
        int threads = 256;
        long total = (long)N * 32;
        int blocks = (int)((total + threads - 1) / threads);
        k_linear<<<blocks, threads>>>(x, W, N, D);
    }
    // 2. degree count
    {
        int threads = 256;
        int work = (E + 3) >> 2;
        int blocks = (work + threads - 1) / threads;
        if (blocks > 16384) blocks = 16384;
        if (blocks < 1) blocks = 1;
        k_deg<<<blocks, threads>>>(dst, E);
    }
    // 3. norm + self-loop init of out
    {
        int threads = 256;
        int blocks = (N + threads - 1) / threads;
        k_norm<<<blocks, threads>>>(out, N);
    }
    // 4. edge messages
    {
        int threads = 256;
        int work = (E + 3) >> 2;
        int blocks = (work + threads - 1) / threads;
        if (blocks > 16384) blocks = 16384;
        if (blocks < 1) blocks = 1;
        k_edge<<<blocks, threads>>>(src, dst, out, E);
    }
}

// round 4
// speedup vs baseline: 1.1746x; 1.1746x over previous
#include <cuda_runtime.h>
#include <cuda_bf16.h>

#define MAX_N 100000
#define DEG_BLOCKS 592   // 4 per SM on 148-SM B200

__device__ float g_h[MAX_N];     // x @ W
__device__ float g_hs[MAX_N];    // dinv * h
__device__ float g_dinv[MAX_N];  // (deg+1)^{-1/2}
__device__ float g_acc[MAX_N];   // sum of hs[src] per dst
__device__ int   g_deg[MAX_N];   // neighbor count (excl. self-loop)

// Fused kernel 1: blocks [0,DEG_BLOCKS) count degrees (grid-stride over edges),
// remaining blocks compute h[i] = dot(x[i,:], W) one warp per node.
// g_deg is pre-zeroed by k_zero (separate tiny launch ordered before).
__global__ void k_lin_deg(const float* __restrict__ x,
                          const float* __restrict__ W,
                          const int* __restrict__ dst,
                          int N, int D, int E) {
    if (blockIdx.x < DEG_BLOCKS) {
        int stride = DEG_BLOCKS * blockDim.x;
        int t = blockIdx.x * blockDim.x + threadIdx.x;
        int E4 = E >> 2;
        const int4* d4 = reinterpret_cast<const int4*>(dst);
        for (int j = t; j < E4; j += stride) {
            int4 d = __ldg(&d4[j]);
            atomicAdd(&g_deg[d.x], 1);
            atomicAdd(&g_deg[d.y], 1);
            atomicAdd(&g_deg[d.z], 1);
            atomicAdd(&g_deg[d.w], 1);
        }
        int base = E4 << 2;
        for (int j = base + t; j < E; j += stride)
            atomicAdd(&g_deg[__ldg(&dst[j])], 1);
        return;
    }
    int gtid = (blockIdx.x - DEG_BLOCKS) * blockDim.x + threadIdx.x;
    int warp = gtid >> 5;
    int lane = gtid & 31;
    if (warp >= N) return;

    const float4* xr = reinterpret_cast<const float4*>(x + (size_t)warp * D);
    const float4* wr = reinterpret_cast<const float4*>(W);
    int nv = D >> 2;
    float acc = 0.0f;
    for (int j = lane; j < nv; j += 32) {
        float4 a = xr[j];
        float4 b = __ldg(&wr[j]);
        acc += a.x * b.x + a.y * b.y + a.z * b.z + a.w * b.w;
    }
#pragma unroll
    for (int o = 16; o; o >>= 1)
        acc += __shfl_xor_sync(0xffffffffu, acc, o);
    if (lane == 0) g_h[warp] = acc;
}

// Kernel 0: zero degree counters (must precede k_lin_deg).
__global__ void k_zero(int N) {
    int i = blockIdx.x * blockDim.x + threadIdx.x;
    if (i < N) g_deg[i] = 0;
}

// Kernel 2: dinv, hs = dinv*h, zero acc.
__global__ void k_norm(int N) {
    int i = blockIdx.x * blockDim.x + threadIdx.x;
    if (i >= N) return;
    float deg = (float)(g_deg[i] + 1);   // self-loop => >= 1
    float di = rsqrtf(deg);
    g_dinv[i] = di;
    g_hs[i] = g_h[i] * di;
    g_acc[i] = 0.0f;
}

// Kernel 3: per-edge: acc[dst] += hs[src].  (dinv[dst] factored out.)
__global__ void k_edge(const int* __restrict__ src,
                       const int* __restrict__ dst, int E) {
    int stride = gridDim.x * blockDim.x;
    int t = blockIdx.x * blockDim.x + threadIdx.x;
    int E4 = E >> 2;
    const int4* s4 = reinterpret_cast<const int4*>(src);
    const int4* d4 = reinterpret_cast<const int4*>(dst);
    for (int j = t; j < E4; j += stride) {
        int4 s = __ldg(&s4[j]);
        int4 d = __ldg(&d4[j]);
        float m0 = g_hs[s.x];
        float m1 = g_hs[s.y];
        float m2 = g_hs[s.z];
        float m3 = g_hs[s.w];
        atomicAdd(&g_acc[d.x], m0);
        atomicAdd(&g_acc[d.y], m1);
        atomicAdd(&g_acc[d.z], m2);
        atomicAdd(&g_acc[d.w], m3);
    }
    int base = E4 << 2;
    for (int j = base + t; j < E; j += stride)
        atomicAdd(&g_acc[__ldg(&dst[j])], g_hs[__ldg(&src[j])]);
}

// Kernel 4: out[i] = dinv[i] * (acc[i] + hs[i])   (self-loop folded in)
__global__ void k_fin(float* __restrict__ out, int N) {
    int i = blockIdx.x * blockDim.x + threadIdx.x;
    if (i >= N) return;
    out[i] = g_dinv[i] * (g_acc[i] + g_hs[i]);
}

extern "C" void kernel_launch(void* const* d_in, const int* in_sizes, int n_in,
                              void* d_out, int out_size) {
    const float* x  = (const float*)d_in[0];
    const int*   ei = (const int*)d_in[1];
    const float* W  = (const float*)d_in[2];
    float* out = (float*)d_out;

    int D = in_sizes[2];               // 512
    if (D <= 0 || (D & 3)) return;
    int N = in_sizes[0] / D;           // 100000
    if (N <= 0 || N > MAX_N || N != out_size) return;
    int E = in_sizes[1] / 2;           // 3200000
    const int* src = ei;
    const int* dst = ei + E;

    const int threads = 256;

    // 0. zero degrees
    k_zero<<<(N + threads - 1) / threads, threads>>>(N);

    // 1. fused: degree count (first DEG_BLOCKS blocks) + linear transform
    {
        int lin_blocks = ((N * 32) + threads - 1) / threads;  // one warp/node
        k_lin_deg<<<DEG_BLOCKS + lin_blocks, threads>>>(x, W, dst, N, D, E);
    }

    // 2. dinv, hs, zero acc
    k_norm<<<(N + threads - 1) / threads, threads>>>(N);

    // 3. edge accumulation
    {
        int work = (E + 3) >> 2;
        int blocks = (work + threads - 1) / threads;
        if (blocks > 16384) blocks = 16384;
        if (blocks < 1) blocks = 1;
        k_edge<<<blocks, threads>>>(src, dst, E);
    }

    // 4. finalize
    k_fin<<<(N + threads - 1) / threads, threads>>>(out, N);
}